// round 15
// baseline (speedup 1.0000x reference)
#include <cuda_runtime.h>
#include <cuda_fp16.h>
#include <math.h>
#include <stdint.h>

// Problem constants
#define BB  2
#define LL  2048
#define DDM 1024
#define HH  16
#define DKK 64
#define MMR (BB * LL)      // 4096 rows

// ---------------- scratch (device globals; no allocation allowed) ----------
__device__ __half g_qh[(size_t)MMR * DDM],  g_ql[(size_t)MMR * DDM];
__device__ __half g_kh[(size_t)MMR * DDM],  g_kl[(size_t)MMR * DDM];
__device__ __half g_vh[(size_t)MMR * DDM],  g_vl[(size_t)MMR * DDM];
__device__ __half g_wqh[(size_t)DDM * DDM], g_wql[(size_t)DDM * DDM];
__device__ __half g_wkh[(size_t)DDM * DDM], g_wkl[(size_t)DDM * DDM];
__device__ __half g_wvh[(size_t)DDM * DDM], g_wvl[(size_t)DDM * DDM];
__device__ __half g_woh[(size_t)DDM * DDM], g_wol[(size_t)DDM * DDM];
__device__ __half g_pqh[(size_t)MMR * DDM], g_pql[(size_t)MMR * DDM];
__device__ __half g_pkh[(size_t)MMR * DDM], g_pkl[(size_t)MMR * DDM];
__device__ __half g_pvh[(size_t)MMR * DDM], g_pvl[(size_t)MMR * DDM];
__device__ __half g_ah[(size_t)MMR * DDM],  g_al[(size_t)MMR * DDM];

// ---------------- helpers ---------------------------------------------------
__device__ __forceinline__ uint32_t smem_u32(const void* p) {
    uint32_t a;
    asm("{ .reg .u64 t; cvta.to.shared.u64 t, %1; cvt.u32.u64 %0, t; }"
        : "=r"(a) : "l"(p));
    return a;
}
__device__ __forceinline__ uint32_t f22h2(float x, float y) {
    __half2 h = __floats2half2_rn(x, y);
    return *reinterpret_cast<uint32_t*>(&h);
}
__device__ __forceinline__ float2 h22f2(uint32_t u) {
    __half2 h = *reinterpret_cast<__half2*>(&u);
    return __half22float2(h);
}
__device__ __forceinline__ void ldsm_x4(uint32_t* d, uint32_t addr) {
    asm volatile("ldmatrix.sync.aligned.m8n8.x4.shared.b16 {%0,%1,%2,%3}, [%4];"
                 : "=r"(d[0]), "=r"(d[1]), "=r"(d[2]), "=r"(d[3]) : "r"(addr));
}
__device__ __forceinline__ void ldsm_x4_t(uint32_t* d, uint32_t addr) {
    asm volatile("ldmatrix.sync.aligned.m8n8.x4.trans.shared.b16 {%0,%1,%2,%3}, [%4];"
                 : "=r"(d[0]), "=r"(d[1]), "=r"(d[2]), "=r"(d[3]) : "r"(addr));
}
__device__ __forceinline__ void mma16816(float* d, const uint32_t* a,
                                         uint32_t b0, uint32_t b1) {
    asm volatile("mma.sync.aligned.m16n8k16.row.col.f32.f16.f16.f32 "
                 "{%0,%1,%2,%3}, {%4,%5,%6,%7}, {%8,%9}, {%0,%1,%2,%3};"
                 : "+f"(d[0]), "+f"(d[1]), "+f"(d[2]), "+f"(d[3])
                 : "r"(a[0]), "r"(a[1]), "r"(a[2]), "r"(a[3]), "r"(b0), "r"(b1));
}
__device__ __forceinline__ void cp16(uint32_t saddr, const void* gaddr) {
    asm volatile("cp.async.cg.shared.global [%0], [%1], 16;"
                 :: "r"(saddr), "l"(gaddr));
}

// ---------------- fp32 -> fp16 hi/lo split (inputs + weights; one launch) ---
__global__ __launch_bounds__(256) void cvt_kernel(
    const float* __restrict__ Q, const float* __restrict__ K,
    const float* __restrict__ V,
    const float* __restrict__ Wq, const float* __restrict__ Wk,
    const float* __restrict__ Wv, const float* __restrict__ Wo)
{
    const float* x;
    __half *hi, *lo;
    int n4;
    const int nI4 = MMR * DDM / 4, nW4 = DDM * DDM / 4;
    switch (blockIdx.y) {
        case 0: x = Q;  hi = g_qh;  lo = g_ql;  n4 = nI4; break;
        case 1: x = K;  hi = g_kh;  lo = g_kl;  n4 = nI4; break;
        case 2: x = V;  hi = g_vh;  lo = g_vl;  n4 = nI4; break;
        case 3: x = Wq; hi = g_wqh; lo = g_wql; n4 = nW4; break;
        case 4: x = Wk; hi = g_wkh; lo = g_wkl; n4 = nW4; break;
        case 5: x = Wv; hi = g_wvh; lo = g_wvl; n4 = nW4; break;
        default: x = Wo; hi = g_woh; lo = g_wol; n4 = nW4; break;
    }
    int i = blockIdx.x * blockDim.x + threadIdx.x;
    if (i >= n4) return;
    float4 v = ((const float4*)x)[i];
    __half h0 = __float2half(v.x), h1 = __float2half(v.y);
    __half h2 = __float2half(v.z), h3 = __float2half(v.w);
    __half l0 = __float2half(v.x - __half2float(h0));
    __half l1 = __float2half(v.y - __half2float(h1));
    __half l2 = __float2half(v.z - __half2float(h2));
    __half l3 = __float2half(v.w - __half2float(h3));
    ((__half2*)hi)[i * 2 + 0] = __halves2half2(h0, h1);
    ((__half2*)hi)[i * 2 + 1] = __halves2half2(h2, h3);
    ((__half2*)lo)[i * 2 + 0] = __halves2half2(l0, l1);
    ((__half2*)lo)[i * 2 + 1] = __halves2half2(l2, l3);
}

// ---------------- raw-mma GEMM, 64x64 warp tiles (unchanged from R14) -------
#define LDHW 72
#define A_T (256 * LDHW)
#define W_T (128 * LDHW)
#define STG (2 * A_T + 2 * W_T)
#define SMEM_GEMM_BYTES (2 * STG * 2)

template<bool HALF_OUT>
__device__ __forceinline__ void gemm_raw(
    const __half* __restrict__ Ah, const __half* __restrict__ Al,
    const __half* __restrict__ Wh, const __half* __restrict__ Wl,
    const float* __restrict__ bias, float* __restrict__ Cf,
    __half* __restrict__ Ch, __half* __restrict__ Cl)
{
    extern __shared__ char smem[];
    const int tid  = threadIdx.x;
    const int w    = tid >> 5, lane = tid & 31;
    const int wm   = w & 3, wn = w >> 2;
    const int g    = lane >> 2, tg = lane & 3;
    const int m0   = blockIdx.y * 256;
    const int n0   = blockIdx.x * 128;
    const uint32_t pool_u = smem_u32(smem);

    float acc[4][8][4];
#pragma unroll
    for (int i = 0; i < 4; i++)
#pragma unroll
        for (int j = 0; j < 8; j++)
#pragma unroll
            for (int e = 0; e < 4; e++) acc[i][j][e] = 0.f;

    auto issue = [&](int c, int stg) {
        const int k0 = c * 64;
        const uint32_t sb = pool_u + (uint32_t)stg * STG * 2;
#pragma unroll
        for (int t = 0; t < 2; t++) {
            const __half* src = t ? Al : Ah;
            const uint32_t ab = sb + (uint32_t)t * A_T * 2;
#pragma unroll
            for (int i = 0; i < 8; i++) {
                int id = i * 256 + tid;
                int r = id >> 3, q = id & 7;
                cp16(ab + (uint32_t)(r * LDHW + q * 8) * 2,
                     &src[(size_t)(m0 + r) * DDM + k0 + q * 8]);
            }
        }
#pragma unroll
        for (int t = 0; t < 2; t++) {
            const __half* src = t ? Wl : Wh;
            const uint32_t ab = sb + (uint32_t)(2 * A_T + t * W_T) * 2;
#pragma unroll
            for (int i = 0; i < 4; i++) {
                int id = i * 256 + tid;
                int r = id >> 3, q = id & 7;
                cp16(ab + (uint32_t)(r * LDHW + q * 8) * 2,
                     &src[(size_t)(n0 + r) * DDM + k0 + q * 8]);
            }
        }
        asm volatile("cp.async.commit_group;");
    };

    const uint32_t abase = ((uint32_t)(lane & 15) * LDHW + (lane >> 4) * 8) * 2;
    const uint32_t bbase = (((lane & 7) + ((lane >> 4) << 3)) * LDHW +
                            ((lane >> 3) & 1) * 8) * 2;

    issue(0, 0);

    for (int c = 0; c < 16; c++) {
        if (c < 15) {
            issue(c + 1, (c + 1) & 1);
            asm volatile("cp.async.wait_group 1;");
        } else {
            asm volatile("cp.async.wait_group 0;");
        }
        __syncthreads();

        const uint32_t sb  = pool_u + (uint32_t)(c & 1) * STG * 2;
        const uint32_t uAh = sb + abase + (uint32_t)((wm * 64) * LDHW) * 2;
        const uint32_t uAl = uAh + (uint32_t)A_T * 2;
        const uint32_t uWh = sb + (uint32_t)(2 * A_T) * 2 + bbase +
                             (uint32_t)((wn * 64) * LDHW) * 2;
        const uint32_t uWl = uWh + (uint32_t)W_T * 2;

#pragma unroll
        for (int kk = 0; kk < 4; kk++) {
            const uint32_t ko = (uint32_t)kk * 32;
            uint32_t ah_[4][4], al_[4][4];
#pragma unroll
            for (int i = 0; i < 4; i++) {
                const uint32_t ro = (uint32_t)(i * 16 * LDHW) * 2 + ko;
                ldsm_x4(ah_[i], uAh + ro);
                ldsm_x4(al_[i], uAl + ro);
            }
#pragma unroll
            for (int jp = 0; jp < 4; jp++) {
                const uint32_t co = (uint32_t)(jp * 16 * LDHW) * 2 + ko;
                uint32_t bh_[4], bl_[4];
                ldsm_x4(bh_, uWh + co);
                ldsm_x4(bl_, uWl + co);
#pragma unroll
                for (int i = 0; i < 4; i++) {
                    float* d0 = acc[i][2 * jp];
                    float* d1 = acc[i][2 * jp + 1];
                    mma16816(d0, ah_[i], bh_[0], bh_[1]);
                    mma16816(d1, ah_[i], bh_[2], bh_[3]);
                    mma16816(d0, ah_[i], bl_[0], bl_[1]);
                    mma16816(d1, ah_[i], bl_[2], bl_[3]);
                    mma16816(d0, al_[i], bh_[0], bh_[1]);
                    mma16816(d1, al_[i], bh_[2], bh_[3]);
                }
            }
        }
        __syncthreads();
    }

#pragma unroll
    for (int i = 0; i < 4; i++) {
        const int rowa = m0 + wm * 64 + i * 16 + g;
        const int rowb = rowa + 8;
#pragma unroll
        for (int jn = 0; jn < 8; jn++) {
            const int col = n0 + wn * 64 + jn * 8 + tg * 2;
            float2 bb = *(const float2*)&bias[col];
            float v0 = acc[i][jn][0] + bb.x;
            float v1 = acc[i][jn][1] + bb.y;
            float v2 = acc[i][jn][2] + bb.x;
            float v3 = acc[i][jn][3] + bb.y;
            if (HALF_OUT) {
                uint32_t hh = f22h2(v0, v1);
                float2 hf = h22f2(hh);
                uint32_t ll = f22h2(v0 - hf.x, v1 - hf.y);
                *(uint32_t*)&Ch[(size_t)rowa * DDM + col] = hh;
                *(uint32_t*)&Cl[(size_t)rowa * DDM + col] = ll;
                hh = f22h2(v2, v3);
                hf = h22f2(hh);
                ll = f22h2(v2 - hf.x, v3 - hf.y);
                *(uint32_t*)&Ch[(size_t)rowb * DDM + col] = hh;
                *(uint32_t*)&Cl[(size_t)rowb * DDM + col] = ll;
            } else {
                *(float2*)&Cf[(size_t)rowa * DDM + col] = make_float2(v0, v1);
                *(float2*)&Cf[(size_t)rowb * DDM + col] = make_float2(v2, v3);
            }
        }
    }
}

__global__ __launch_bounds__(256, 1) void qkv_wmma_kernel(
    const float* __restrict__ bq, const float* __restrict__ bk,
    const float* __restrict__ bv)
{
    if (blockIdx.z == 0)
        gemm_raw<true>(g_qh, g_ql, g_wqh, g_wql, bq, nullptr, g_pqh, g_pql);
    else if (blockIdx.z == 1)
        gemm_raw<true>(g_kh, g_kl, g_wkh, g_wkl, bk, nullptr, g_pkh, g_pkl);
    else
        gemm_raw<true>(g_vh, g_vl, g_wvh, g_wvl, bv, nullptr, g_pvh, g_pvl);
}

__global__ __launch_bounds__(256, 1) void out_wmma_kernel(
    const float* __restrict__ bo, float* __restrict__ out)
{
    gemm_raw<false>(g_ah, g_al, g_woh, g_wol, bo, out, nullptr, nullptr);
}

// ---------------------------------------------------------------------------
// FA-2 attention v2: CTA = 256 q-rows, 8 warps x 32 rows (2 m-tiles each).
// K/V fragments reused across both m-tiles -> half the smem-read traffic.
// ---------------------------------------------------------------------------
#define KLD 72
#define KVBUF (4 * 64 * KLD)
#define QBUF (2 * 256 * KLD)
#define ATTN_SMEM_BYTES (QBUF * 2)   // 73728 B; KV ring (2*KVBUF*2) == same

__global__ __launch_bounds__(256) void attn_mma_kernel()
{
    extern __shared__ __half spool[];
    const int tid  = threadIdx.x;
    const int w    = tid >> 5, lane = tid & 31;
    const int g    = lane >> 2, tg = lane & 3;
    const int qblk = gridDim.x - 1 - blockIdx.x;    // big tiles first
    const int bh   = blockIdx.y;
    const int b    = bh >> 4, h = bh & 15;
    const int qbase = qblk * 256;
    const int r0    = w * 32;
    const int ntiles = 4 * qblk + 4;

    const size_t headoff = (size_t)b * LL * DDM + (size_t)h * DKK;
    const __half* qhg = g_pqh + headoff;
    const __half* qlg = g_pql + headoff;
    const __half* khg = g_pkh + headoff;
    const __half* klg = g_pkl + headoff;
    const __half* vhg = g_pvh + headoff;
    const __half* vlg = g_pvl + headoff;

    const uint32_t pool_u = smem_u32(spool);

    // ---- stage Q (scaled by 1/8) for 256 rows, extract frags, free smem ----
    {
        __half* sQh = spool;                 // 256 x KLD
        __half* sQl = spool + 256 * KLD;
        const __half2 sc = __float2half2_rn(0.125f);
#pragma unroll
        for (int p = 0; p < 8; p++) {
            int id = p * 256 + tid;          // 0..2047
            int r = id >> 3, c8 = (id & 7) * 8;
            float4 vh = *(const float4*)&qhg[(size_t)(qbase + r) * DDM + c8];
            float4 vl = *(const float4*)&qlg[(size_t)(qbase + r) * DDM + c8];
            __half2* hp = (__half2*)&vh;
            __half2* lp = (__half2*)&vl;
#pragma unroll
            for (int e = 0; e < 4; e++) {
                hp[e] = __hmul2(hp[e], sc);
                lp[e] = __hmul2(lp[e], sc);
            }
            *(float4*)&sQh[r * KLD + c8] = vh;
            *(float4*)&sQl[r * KLD + c8] = vl;
        }
    }
    __syncthreads();

    uint32_t qfh[2][4][4], qfl[2][4][4];     // [m-tile][kk][frag]
#pragma unroll
    for (int i = 0; i < 2; i++) {
        uint32_t qoff = ((uint32_t)(r0 + i * 16 + (lane & 15)) * KLD +
                         (lane >> 4) * 8) * 2;
#pragma unroll
        for (int kk = 0; kk < 4; kk++) {
            ldsm_x4(qfh[i][kk], pool_u + qoff + kk * 32);
            ldsm_x4(qfl[i][kk], pool_u + (uint32_t)(256 * KLD) * 2 + qoff + kk * 32);
        }
    }
    __syncthreads();   // Q frags in regs; smem pool now the KV ring

    const uint32_t oKh = 0, oKl = 64 * KLD, oVh = 2 * 64 * KLD, oVl = 3 * 64 * KLD;
    const int ld_r = tid >> 2;
    const int ld_c = (tid & 3) * 16;
    const uint32_t sObase = ((uint32_t)ld_r * KLD + ld_c) * 2;

    auto issue_tile = [&](int kt, int buf) {
        const size_t go = (size_t)(kt * 64 + ld_r) * DDM + ld_c;
        const uint32_t sb = pool_u + (uint32_t)buf * KVBUF * 2 + sObase;
        cp16(sb + oKh * 2,      khg + go);
        cp16(sb + oKh * 2 + 16, khg + go + 8);
        cp16(sb + oKl * 2,      klg + go);
        cp16(sb + oKl * 2 + 16, klg + go + 8);
        cp16(sb + oVh * 2,      vhg + go);
        cp16(sb + oVh * 2 + 16, vhg + go + 8);
        cp16(sb + oVl * 2,      vlg + go);
        cp16(sb + oVl * 2 + 16, vlg + go + 8);
        asm volatile("cp.async.commit_group;");
    };

    const uint32_t kbasea = (((lane & 7) + ((lane >> 4) << 3)) * KLD +
                             ((lane >> 3) & 1) * 8) * 2;
    const uint32_t vbasea = ((lane & 15) * KLD + (lane >> 4) * 8) * 2;

    float o[2][8][4];
#pragma unroll
    for (int i = 0; i < 2; i++)
#pragma unroll
        for (int jn = 0; jn < 8; jn++)
#pragma unroll
            for (int e = 0; e < 4; e++) o[i][jn][e] = 0.f;
    float m_r[2][2], l_r[2][2];
#pragma unroll
    for (int i = 0; i < 2; i++) {
        m_r[i][0] = -INFINITY; m_r[i][1] = -INFINITY;
        l_r[i][0] = 0.f;       l_r[i][1] = 0.f;
    }

    issue_tile(0, 0);

    for (int kt = 0; kt < ntiles; kt++) {
        __syncthreads();
        if (kt + 1 < ntiles) {
            issue_tile(kt + 1, (kt + 1) & 1);
            asm volatile("cp.async.wait_group 1;");
        } else {
            asm volatile("cp.async.wait_group 0;");
        }
        __syncthreads();

        const uint32_t bufu = pool_u + (uint32_t)(kt & 1) * KVBUF * 2;
        const uint32_t ku_h = bufu + oKh * 2, ku_l = bufu + oKl * 2;
        const uint32_t vu_h = bufu + oVh * 2, vu_l = bufu + oVl * 2;

        // ---- S = Q K^T (both m-tiles share K fragments) ----
        float s[2][8][4];
#pragma unroll
        for (int i = 0; i < 2; i++)
#pragma unroll
            for (int jn = 0; jn < 8; jn++)
#pragma unroll
                for (int e = 0; e < 4; e++) s[i][jn][e] = 0.f;

#pragma unroll
        for (int kk = 0; kk < 4; kk++) {
#pragma unroll
            for (int jp = 0; jp < 4; jp++) {
                const uint32_t koff = ((uint32_t)(jp * 16) * KLD + kk * 16) * 2;
                uint32_t bh_[4], bl_[4];
                ldsm_x4(bh_, ku_h + kbasea + koff);
                ldsm_x4(bl_, ku_l + kbasea + koff);
#pragma unroll
                for (int i = 0; i < 2; i++) {
                    float* d0 = s[i][2 * jp];
                    float* d1 = s[i][2 * jp + 1];
                    mma16816(d0, qfh[i][kk], bh_[0], bh_[1]);
                    mma16816(d1, qfh[i][kk], bh_[2], bh_[3]);
                    mma16816(d0, qfh[i][kk], bl_[0], bl_[1]);
                    mma16816(d1, qfh[i][kk], bl_[2], bl_[3]);
                    mma16816(d0, qfl[i][kk], bh_[0], bh_[1]);
                    mma16816(d1, qfl[i][kk], bh_[2], bh_[3]);
                }
            }
        }

        // ---- causal mask (warp-exact gating) ----
        const int kb = kt * 64;
        if (kb + 63 > qbase + r0) {
#pragma unroll
            for (int i = 0; i < 2; i++) {
                const int rowa = qbase + r0 + i * 16 + g;
                const int rowb = rowa + 8;
#pragma unroll
                for (int jn = 0; jn < 8; jn++) {
                    const int c0 = kb + jn * 8 + tg * 2;
                    if (c0     > rowa) s[i][jn][0] = -INFINITY;
                    if (c0 + 1 > rowa) s[i][jn][1] = -INFINITY;
                    if (c0     > rowb) s[i][jn][2] = -INFINITY;
                    if (c0 + 1 > rowb) s[i][jn][3] = -INFINITY;
                }
            }
        }

        // ---- online softmax + P frags per m-tile ----
        uint32_t pah[2][4][4], pal[2][4][4];
#pragma unroll
        for (int i = 0; i < 2; i++) {
            float mxa = -INFINITY, mxb = -INFINITY;
#pragma unroll
            for (int jn = 0; jn < 8; jn++) {
                mxa = fmaxf(mxa, fmaxf(s[i][jn][0], s[i][jn][1]));
                mxb = fmaxf(mxb, fmaxf(s[i][jn][2], s[i][jn][3]));
            }
            mxa = fmaxf(mxa, __shfl_xor_sync(0xffffffffu, mxa, 1));
            mxa = fmaxf(mxa, __shfl_xor_sync(0xffffffffu, mxa, 2));
            mxb = fmaxf(mxb, __shfl_xor_sync(0xffffffffu, mxb, 1));
            mxb = fmaxf(mxb, __shfl_xor_sync(0xffffffffu, mxb, 2));
            const float mna = fmaxf(m_r[i][0], mxa);
            const float mnb = fmaxf(m_r[i][1], mxb);
            float suma = 0.f, sumb = 0.f;
#pragma unroll
            for (int jn = 0; jn < 8; jn++) {
                s[i][jn][0] = __expf(s[i][jn][0] - mna);
                s[i][jn][1] = __expf(s[i][jn][1] - mna);
                s[i][jn][2] = __expf(s[i][jn][2] - mnb);
                s[i][jn][3] = __expf(s[i][jn][3] - mnb);
                suma += s[i][jn][0] + s[i][jn][1];
                sumb += s[i][jn][2] + s[i][jn][3];
            }
            suma += __shfl_xor_sync(0xffffffffu, suma, 1);
            suma += __shfl_xor_sync(0xffffffffu, suma, 2);
            sumb += __shfl_xor_sync(0xffffffffu, sumb, 1);
            sumb += __shfl_xor_sync(0xffffffffu, sumb, 2);
            const float aa = __expf(m_r[i][0] - mna);
            const float ab = __expf(m_r[i][1] - mnb);
            m_r[i][0] = mna; m_r[i][1] = mnb;
            l_r[i][0] = l_r[i][0] * aa + suma;
            l_r[i][1] = l_r[i][1] * ab + sumb;
#pragma unroll
            for (int jn = 0; jn < 8; jn++) {
                o[i][jn][0] *= aa; o[i][jn][1] *= aa;
                o[i][jn][2] *= ab; o[i][jn][3] *= ab;
            }
#pragma unroll
            for (int jk = 0; jk < 4; jk++) {
                const float* p0 = s[i][2 * jk];
                const float* p1 = s[i][2 * jk + 1];
                pah[i][jk][0] = f22h2(p0[0], p0[1]);
                pah[i][jk][1] = f22h2(p0[2], p0[3]);
                pah[i][jk][2] = f22h2(p1[0], p1[1]);
                pah[i][jk][3] = f22h2(p1[2], p1[3]);
                float2 r;
                r = h22f2(pah[i][jk][0]); pal[i][jk][0] = f22h2(p0[0] - r.x, p0[1] - r.y);
                r = h22f2(pah[i][jk][1]); pal[i][jk][1] = f22h2(p0[2] - r.x, p0[3] - r.y);
                r = h22f2(pah[i][jk][2]); pal[i][jk][2] = f22h2(p1[0] - r.x, p1[1] - r.y);
                r = h22f2(pah[i][jk][3]); pal[i][jk][3] = f22h2(p1[2] - r.x, p1[3] - r.y);
            }
        }

        // ---- O += P V (both m-tiles share V fragments) ----
#pragma unroll
        for (int jk = 0; jk < 4; jk++) {
#pragma unroll
            for (int jp = 0; jp < 4; jp++) {
                const uint32_t voff = ((uint32_t)(jk * 16) * KLD + jp * 16) * 2;
                uint32_t bh_[4], bl_[4];
                ldsm_x4_t(bh_, vu_h + vbasea + voff);
                ldsm_x4_t(bl_, vu_l + vbasea + voff);
#pragma unroll
                for (int i = 0; i < 2; i++) {
                    float* d0 = o[i][2 * jp];
                    float* d1 = o[i][2 * jp + 1];
                    mma16816(d0, pah[i][jk], bh_[0], bh_[1]);
                    mma16816(d1, pah[i][jk], bh_[2], bh_[3]);
                    mma16816(d0, pah[i][jk], bl_[0], bl_[1]);
                    mma16816(d1, pah[i][jk], bl_[2], bl_[3]);
                    mma16816(d0, pal[i][jk], bh_[0], bh_[1]);
                    mma16816(d1, pal[i][jk], bh_[2], bh_[3]);
                }
            }
        }
    }

    // ---- epilogue: normalize, split hi/lo, store ----
#pragma unroll
    for (int i = 0; i < 2; i++) {
        const float inva = 1.f / l_r[i][0];
        const float invb = 1.f / l_r[i][1];
        const int rowa = qbase + r0 + i * 16 + g;
        const size_t basea = (size_t)(b * LL + rowa) * DDM + h * DKK;
        const size_t baseb = basea + (size_t)8 * DDM;
#pragma unroll
        for (int jn = 0; jn < 8; jn++) {
            const int c = jn * 8 + tg * 2;
            float v0 = o[i][jn][0] * inva, v1 = o[i][jn][1] * inva;
            uint32_t hh = f22h2(v0, v1);
            float2 hf = h22f2(hh);
            uint32_t ll = f22h2(v0 - hf.x, v1 - hf.y);
            *(uint32_t*)&g_ah[basea + c] = hh;
            *(uint32_t*)&g_al[basea + c] = ll;
            v0 = o[i][jn][2] * invb; v1 = o[i][jn][3] * invb;
            hh = f22h2(v0, v1);
            hf = h22f2(hh);
            ll = f22h2(v0 - hf.x, v1 - hf.y);
            *(uint32_t*)&g_ah[baseb + c] = hh;
            *(uint32_t*)&g_al[baseb + c] = ll;
        }
    }
}

// ---------------------------------------------------------------------------
// Inputs (metadata order): Q, K, V, mask, Wq, bq, Wk, bk, Wv, bv, Wo, bo.
// ---------------------------------------------------------------------------
extern "C" void kernel_launch(void* const* d_in, const int* in_sizes, int n_in,
                              void* d_out, int out_size)
{
    const float* Q  = (const float*)d_in[0];
    const float* K  = (const float*)d_in[1];
    const float* V  = (const float*)d_in[2];
    const float* Wq = (const float*)d_in[4];
    const float* bq = (const float*)d_in[5];
    const float* Wk = (const float*)d_in[6];
    const float* bk = (const float*)d_in[7];
    const float* Wv = (const float*)d_in[8];
    const float* bv = (const float*)d_in[9];
    const float* Wo = (const float*)d_in[10];
    const float* bo = (const float*)d_in[11];
    float* out = (float*)d_out;

    cudaFuncSetAttribute(qkv_wmma_kernel,
                         cudaFuncAttributeMaxDynamicSharedMemorySize, SMEM_GEMM_BYTES);
    cudaFuncSetAttribute(out_wmma_kernel,
                         cudaFuncAttributeMaxDynamicSharedMemorySize, SMEM_GEMM_BYTES);
    cudaFuncSetAttribute(attn_mma_kernel,
                         cudaFuncAttributeMaxDynamicSharedMemorySize, ATTN_SMEM_BYTES);

    const int nI4 = MMR * DDM / 4;

    dim3 gcvt(nI4 / 256, 7);
    cvt_kernel<<<gcvt, 256>>>(Q, K, V, Wq, Wk, Wv, Wo);

    dim3 gqkv(DDM / 128, MMR / 256, 3);
    qkv_wmma_kernel<<<gqkv, 256, SMEM_GEMM_BYTES>>>(bq, bk, bv);

    dim3 gattn(LL / 256, BB * HH);
    attn_mma_kernel<<<gattn, 256, ATTN_SMEM_BYTES>>>();

    dim3 gout(DDM / 128, MMR / 256);
    out_wmma_kernel<<<gout, 256, SMEM_GEMM_BYTES>>>(bo, out);
}

// round 16
// speedup vs baseline: 1.0573x; 1.0573x over previous
#include <cuda_runtime.h>
#include <cuda_fp16.h>
#include <math.h>
#include <stdint.h>

// Problem constants
#define BB  2
#define LL  2048
#define DDM 1024
#define HH  16
#define DKK 64
#define MMR (BB * LL)      // 4096 rows

// ---------------- scratch (device globals; no allocation allowed) ----------
__device__ __half g_qh[(size_t)MMR * DDM],  g_ql[(size_t)MMR * DDM];
__device__ __half g_kh[(size_t)MMR * DDM],  g_kl[(size_t)MMR * DDM];
__device__ __half g_vh[(size_t)MMR * DDM],  g_vl[(size_t)MMR * DDM];
__device__ __half g_wqh[(size_t)DDM * DDM], g_wql[(size_t)DDM * DDM];
__device__ __half g_wkh[(size_t)DDM * DDM], g_wkl[(size_t)DDM * DDM];
__device__ __half g_wvh[(size_t)DDM * DDM], g_wvl[(size_t)DDM * DDM];
__device__ __half g_woh[(size_t)DDM * DDM], g_wol[(size_t)DDM * DDM];
__device__ __half g_pqh[(size_t)MMR * DDM], g_pql[(size_t)MMR * DDM];
__device__ __half g_pkh[(size_t)MMR * DDM], g_pkl[(size_t)MMR * DDM];
__device__ __half g_pvh[(size_t)MMR * DDM], g_pvl[(size_t)MMR * DDM];
__device__ __half g_ah[(size_t)MMR * DDM],  g_al[(size_t)MMR * DDM];

// ---------------- helpers ---------------------------------------------------
__device__ __forceinline__ uint32_t smem_u32(const void* p) {
    uint32_t a;
    asm("{ .reg .u64 t; cvta.to.shared.u64 t, %1; cvt.u32.u64 %0, t; }"
        : "=r"(a) : "l"(p));
    return a;
}
__device__ __forceinline__ uint32_t f22h2(float x, float y) {
    __half2 h = __floats2half2_rn(x, y);
    return *reinterpret_cast<uint32_t*>(&h);
}
__device__ __forceinline__ float2 h22f2(uint32_t u) {
    __half2 h = *reinterpret_cast<__half2*>(&u);
    return __half22float2(h);
}
__device__ __forceinline__ void ldsm_x4(uint32_t* d, uint32_t addr) {
    asm volatile("ldmatrix.sync.aligned.m8n8.x4.shared.b16 {%0,%1,%2,%3}, [%4];"
                 : "=r"(d[0]), "=r"(d[1]), "=r"(d[2]), "=r"(d[3]) : "r"(addr));
}
__device__ __forceinline__ void ldsm_x4_t(uint32_t* d, uint32_t addr) {
    asm volatile("ldmatrix.sync.aligned.m8n8.x4.trans.shared.b16 {%0,%1,%2,%3}, [%4];"
                 : "=r"(d[0]), "=r"(d[1]), "=r"(d[2]), "=r"(d[3]) : "r"(addr));
}
__device__ __forceinline__ void mma16816(float* d, const uint32_t* a,
                                         uint32_t b0, uint32_t b1) {
    asm volatile("mma.sync.aligned.m16n8k16.row.col.f32.f16.f16.f32 "
                 "{%0,%1,%2,%3}, {%4,%5,%6,%7}, {%8,%9}, {%0,%1,%2,%3};"
                 : "+f"(d[0]), "+f"(d[1]), "+f"(d[2]), "+f"(d[3])
                 : "r"(a[0]), "r"(a[1]), "r"(a[2]), "r"(a[3]), "r"(b0), "r"(b1));
}
__device__ __forceinline__ void cp16(uint32_t saddr, const void* gaddr) {
    asm volatile("cp.async.cg.shared.global [%0], [%1], 16;"
                 :: "r"(saddr), "l"(gaddr));
}

// ---------------- fp32 -> fp16 hi/lo split (inputs + weights; one launch) ---
__global__ __launch_bounds__(256) void cvt_kernel(
    const float* __restrict__ Q, const float* __restrict__ K,
    const float* __restrict__ V,
    const float* __restrict__ Wq, const float* __restrict__ Wk,
    const float* __restrict__ Wv, const float* __restrict__ Wo)
{
    const float* x;
    __half *hi, *lo;
    int n4;
    const int nI4 = MMR * DDM / 4, nW4 = DDM * DDM / 4;
    switch (blockIdx.y) {
        case 0: x = Q;  hi = g_qh;  lo = g_ql;  n4 = nI4; break;
        case 1: x = K;  hi = g_kh;  lo = g_kl;  n4 = nI4; break;
        case 2: x = V;  hi = g_vh;  lo = g_vl;  n4 = nI4; break;
        case 3: x = Wq; hi = g_wqh; lo = g_wql; n4 = nW4; break;
        case 4: x = Wk; hi = g_wkh; lo = g_wkl; n4 = nW4; break;
        case 5: x = Wv; hi = g_wvh; lo = g_wvl; n4 = nW4; break;
        default: x = Wo; hi = g_woh; lo = g_wol; n4 = nW4; break;
    }
    int i = blockIdx.x * blockDim.x + threadIdx.x;
    if (i >= n4) return;
    float4 v = ((const float4*)x)[i];
    __half h0 = __float2half(v.x), h1 = __float2half(v.y);
    __half h2 = __float2half(v.z), h3 = __float2half(v.w);
    __half l0 = __float2half(v.x - __half2float(h0));
    __half l1 = __float2half(v.y - __half2float(h1));
    __half l2 = __float2half(v.z - __half2float(h2));
    __half l3 = __float2half(v.w - __half2float(h3));
    ((__half2*)hi)[i * 2 + 0] = __halves2half2(h0, h1);
    ((__half2*)hi)[i * 2 + 1] = __halves2half2(h2, h3);
    ((__half2*)lo)[i * 2 + 0] = __halves2half2(l0, l1);
    ((__half2*)lo)[i * 2 + 1] = __halves2half2(l2, l3);
}

// ---------------- raw-mma GEMM, 64x64 warp tiles (R14 + mma reorder) --------
#define LDHW 72
#define A_T (256 * LDHW)
#define W_T (128 * LDHW)
#define STG (2 * A_T + 2 * W_T)
#define SMEM_GEMM_BYTES (2 * STG * 2)

template<bool HALF_OUT>
__device__ __forceinline__ void gemm_raw(
    const __half* __restrict__ Ah, const __half* __restrict__ Al,
    const __half* __restrict__ Wh, const __half* __restrict__ Wl,
    const float* __restrict__ bias, float* __restrict__ Cf,
    __half* __restrict__ Ch, __half* __restrict__ Cl)
{
    extern __shared__ char smem[];
    const int tid  = threadIdx.x;
    const int w    = tid >> 5, lane = tid & 31;
    const int wm   = w & 3, wn = w >> 2;
    const int g    = lane >> 2, tg = lane & 3;
    const int m0   = blockIdx.y * 256;
    const int n0   = blockIdx.x * 128;
    const uint32_t pool_u = smem_u32(smem);

    float acc[4][8][4];
#pragma unroll
    for (int i = 0; i < 4; i++)
#pragma unroll
        for (int j = 0; j < 8; j++)
#pragma unroll
            for (int e = 0; e < 4; e++) acc[i][j][e] = 0.f;

    auto issue = [&](int c, int stg) {
        const int k0 = c * 64;
        const uint32_t sb = pool_u + (uint32_t)stg * STG * 2;
#pragma unroll
        for (int t = 0; t < 2; t++) {
            const __half* src = t ? Al : Ah;
            const uint32_t ab = sb + (uint32_t)t * A_T * 2;
#pragma unroll
            for (int i = 0; i < 8; i++) {
                int id = i * 256 + tid;
                int r = id >> 3, q = id & 7;
                cp16(ab + (uint32_t)(r * LDHW + q * 8) * 2,
                     &src[(size_t)(m0 + r) * DDM + k0 + q * 8]);
            }
        }
#pragma unroll
        for (int t = 0; t < 2; t++) {
            const __half* src = t ? Wl : Wh;
            const uint32_t ab = sb + (uint32_t)(2 * A_T + t * W_T) * 2;
#pragma unroll
            for (int i = 0; i < 4; i++) {
                int id = i * 256 + tid;
                int r = id >> 3, q = id & 7;
                cp16(ab + (uint32_t)(r * LDHW + q * 8) * 2,
                     &src[(size_t)(n0 + r) * DDM + k0 + q * 8]);
            }
        }
        asm volatile("cp.async.commit_group;");
    };

    const uint32_t abase = ((uint32_t)(lane & 15) * LDHW + (lane >> 4) * 8) * 2;
    const uint32_t bbase = (((lane & 7) + ((lane >> 4) << 3)) * LDHW +
                            ((lane >> 3) & 1) * 8) * 2;

    issue(0, 0);

    for (int c = 0; c < 16; c++) {
        if (c < 15) {
            issue(c + 1, (c + 1) & 1);
            asm volatile("cp.async.wait_group 1;");
        } else {
            asm volatile("cp.async.wait_group 0;");
        }
        __syncthreads();

        const uint32_t sb  = pool_u + (uint32_t)(c & 1) * STG * 2;
        const uint32_t uAh = sb + abase + (uint32_t)((wm * 64) * LDHW) * 2;
        const uint32_t uAl = uAh + (uint32_t)A_T * 2;
        const uint32_t uWh = sb + (uint32_t)(2 * A_T) * 2 + bbase +
                             (uint32_t)((wn * 64) * LDHW) * 2;
        const uint32_t uWl = uWh + (uint32_t)W_T * 2;

#pragma unroll
        for (int kk = 0; kk < 4; kk++) {
            const uint32_t ko = (uint32_t)kk * 32;
            uint32_t ah_[4][4], al_[4][4];
#pragma unroll
            for (int i = 0; i < 4; i++) {
                const uint32_t ro = (uint32_t)(i * 16 * LDHW) * 2 + ko;
                ldsm_x4(ah_[i], uAh + ro);
                ldsm_x4(al_[i], uAl + ro);
            }
#pragma unroll
            for (int jp = 0; jp < 4; jp++) {
                const uint32_t co = (uint32_t)(jp * 16 * LDHW) * 2 + ko;
                uint32_t bh_[4], bl_[4];
                ldsm_x4(bh_, uWh + co);
                ldsm_x4(bl_, uWl + co);
                // Reordered: product-type outer, m-tile inner -> same-acc
                // reuse distance 8 instead of 2 (hide HMMA latency).
#pragma unroll
                for (int i = 0; i < 4; i++)
                    mma16816(acc[i][2 * jp],     ah_[i], bh_[0], bh_[1]);
#pragma unroll
                for (int i = 0; i < 4; i++)
                    mma16816(acc[i][2 * jp + 1], ah_[i], bh_[2], bh_[3]);
#pragma unroll
                for (int i = 0; i < 4; i++)
                    mma16816(acc[i][2 * jp],     ah_[i], bl_[0], bl_[1]);
#pragma unroll
                for (int i = 0; i < 4; i++)
                    mma16816(acc[i][2 * jp + 1], ah_[i], bl_[2], bl_[3]);
#pragma unroll
                for (int i = 0; i < 4; i++)
                    mma16816(acc[i][2 * jp],     al_[i], bh_[0], bh_[1]);
#pragma unroll
                for (int i = 0; i < 4; i++)
                    mma16816(acc[i][2 * jp + 1], al_[i], bh_[2], bh_[3]);
            }
        }
        __syncthreads();
    }

#pragma unroll
    for (int i = 0; i < 4; i++) {
        const int rowa = m0 + wm * 64 + i * 16 + g;
        const int rowb = rowa + 8;
#pragma unroll
        for (int jn = 0; jn < 8; jn++) {
            const int col = n0 + wn * 64 + jn * 8 + tg * 2;
            float2 bb = *(const float2*)&bias[col];
            float v0 = acc[i][jn][0] + bb.x;
            float v1 = acc[i][jn][1] + bb.y;
            float v2 = acc[i][jn][2] + bb.x;
            float v3 = acc[i][jn][3] + bb.y;
            if (HALF_OUT) {
                uint32_t hh = f22h2(v0, v1);
                float2 hf = h22f2(hh);
                uint32_t ll = f22h2(v0 - hf.x, v1 - hf.y);
                *(uint32_t*)&Ch[(size_t)rowa * DDM + col] = hh;
                *(uint32_t*)&Cl[(size_t)rowa * DDM + col] = ll;
                hh = f22h2(v2, v3);
                hf = h22f2(hh);
                ll = f22h2(v2 - hf.x, v3 - hf.y);
                *(uint32_t*)&Ch[(size_t)rowb * DDM + col] = hh;
                *(uint32_t*)&Cl[(size_t)rowb * DDM + col] = ll;
            } else {
                *(float2*)&Cf[(size_t)rowa * DDM + col] = make_float2(v0, v1);
                *(float2*)&Cf[(size_t)rowb * DDM + col] = make_float2(v2, v3);
            }
        }
    }
}

__global__ __launch_bounds__(256, 1) void qkv_wmma_kernel(
    const float* __restrict__ bq, const float* __restrict__ bk,
    const float* __restrict__ bv)
{
    if (blockIdx.z == 0)
        gemm_raw<true>(g_qh, g_ql, g_wqh, g_wql, bq, nullptr, g_pqh, g_pql);
    else if (blockIdx.z == 1)
        gemm_raw<true>(g_kh, g_kl, g_wkh, g_wkl, bk, nullptr, g_pkh, g_pkl);
    else
        gemm_raw<true>(g_vh, g_vl, g_wvh, g_wvl, bv, nullptr, g_pvh, g_pvl);
}

__global__ __launch_bounds__(256, 1) void out_wmma_kernel(
    const float* __restrict__ bo, float* __restrict__ out)
{
    gemm_raw<false>(g_ah, g_al, g_woh, g_wol, bo, out, nullptr, nullptr);
}

// ---------------------------------------------------------------------------
// FA-2 attention (R14 config: CTA = 128 q-rows, 8 warps x 16 rows; proven).
// ---------------------------------------------------------------------------
#define KLD 72
#define KVBUF (4 * 64 * KLD)
#define ATTN_SMEM_BYTES (2 * KVBUF * 2)

__global__ __launch_bounds__(256) void attn_mma_kernel()
{
    extern __shared__ __half spool[];
    const int tid  = threadIdx.x;
    const int w    = tid >> 5, lane = tid & 31;
    const int g    = lane >> 2, tg = lane & 3;
    const int qblk = gridDim.x - 1 - blockIdx.x;
    const int bh   = blockIdx.y;
    const int b    = bh >> 4, h = bh & 15;
    const int qbase = qblk * 128;
    const int r0    = w * 16;
    const int ntiles = 2 * qblk + 2;

    const size_t headoff = (size_t)b * LL * DDM + (size_t)h * DKK;
    const __half* qhg = g_pqh + headoff;
    const __half* qlg = g_pql + headoff;
    const __half* khg = g_pkh + headoff;
    const __half* klg = g_pkl + headoff;
    const __half* vhg = g_pvh + headoff;
    const __half* vlg = g_pvl + headoff;

    const uint32_t pool_u = smem_u32(spool);

    {
        __half* sQh = spool;
        __half* sQl = spool + 128 * KLD;
        const __half2 sc = __float2half2_rn(0.125f);
#pragma unroll
        for (int p = 0; p < 2; p++) {
            int id = p * 256 + tid;
            int r = id >> 2, c16 = (id & 3) * 16;
#pragma unroll
            for (int u = 0; u < 2; u++) {
                float4 vh = *(const float4*)&qhg[(size_t)(qbase + r) * DDM + c16 + u * 8];
                float4 vl = *(const float4*)&qlg[(size_t)(qbase + r) * DDM + c16 + u * 8];
                __half2* hp = (__half2*)&vh;
                __half2* lp = (__half2*)&vl;
#pragma unroll
                for (int e = 0; e < 4; e++) {
                    hp[e] = __hmul2(hp[e], sc);
                    lp[e] = __hmul2(lp[e], sc);
                }
                *(float4*)&sQh[r * KLD + c16 + u * 8] = vh;
                *(float4*)&sQl[r * KLD + c16 + u * 8] = vl;
            }
        }
    }
    __syncthreads();

    uint32_t qfh[4][4], qfl[4][4];
    {
        uint32_t qoff = ((uint32_t)(r0 + (lane & 15)) * KLD + (lane >> 4) * 8) * 2;
#pragma unroll
        for (int kk = 0; kk < 4; kk++) {
            ldsm_x4(qfh[kk], pool_u + qoff + kk * 32);
            ldsm_x4(qfl[kk], pool_u + (uint32_t)(128 * KLD) * 2 + qoff + kk * 32);
        }
    }
    __syncthreads();

    const uint32_t oKh = 0, oKl = 64 * KLD, oVh = 2 * 64 * KLD, oVl = 3 * 64 * KLD;

    const int ld_r  = tid >> 2;
    const int ld_c  = (tid & 3) * 16;
    const uint32_t sObase = ((uint32_t)ld_r * KLD + ld_c) * 2;

    auto issue_tile = [&](int kt, int buf) {
        const size_t go = (size_t)(kt * 64 + ld_r) * DDM + ld_c;
        const uint32_t sb = pool_u + (uint32_t)buf * KVBUF * 2 + sObase;
        cp16(sb + oKh * 2,      khg + go);
        cp16(sb + oKh * 2 + 16, khg + go + 8);
        cp16(sb + oKl * 2,      klg + go);
        cp16(sb + oKl * 2 + 16, klg + go + 8);
        cp16(sb + oVh * 2,      vhg + go);
        cp16(sb + oVh * 2 + 16, vhg + go + 8);
        cp16(sb + oVl * 2,      vlg + go);
        cp16(sb + oVl * 2 + 16, vlg + go + 8);
        asm volatile("cp.async.commit_group;");
    };

    const uint32_t kbasea = (((lane & 7) + ((lane >> 4) << 3)) * KLD +
                             ((lane >> 3) & 1) * 8) * 2;
    const uint32_t vbasea = ((lane & 15) * KLD + (lane >> 4) * 8) * 2;

    float o[8][4];
#pragma unroll
    for (int jn = 0; jn < 8; jn++)
#pragma unroll
        for (int e = 0; e < 4; e++) o[jn][e] = 0.f;
    float m_a = -INFINITY, m_b = -INFINITY, l_a = 0.f, l_b = 0.f;

    issue_tile(0, 0);

    for (int kt = 0; kt < ntiles; kt++) {
        __syncthreads();
        if (kt + 1 < ntiles) {
            issue_tile(kt + 1, (kt + 1) & 1);
            asm volatile("cp.async.wait_group 1;");
        } else {
            asm volatile("cp.async.wait_group 0;");
        }
        __syncthreads();

        const uint32_t bufu = pool_u + (uint32_t)(kt & 1) * KVBUF * 2;
        const uint32_t ku_h = bufu + oKh * 2, ku_l = bufu + oKl * 2;
        const uint32_t vu_h = bufu + oVh * 2, vu_l = bufu + oVl * 2;

        float s[8][4];
#pragma unroll
        for (int jn = 0; jn < 8; jn++)
#pragma unroll
            for (int e = 0; e < 4; e++) s[jn][e] = 0.f;

#pragma unroll
        for (int kk = 0; kk < 4; kk++) {
#pragma unroll
            for (int jp = 0; jp < 4; jp++) {
                const uint32_t koff = ((uint32_t)(jp * 16) * KLD + kk * 16) * 2;
                uint32_t bh_[4], bl_[4];
                ldsm_x4(bh_, ku_h + kbasea + koff);
                ldsm_x4(bl_, ku_l + kbasea + koff);
                mma16816(s[2 * jp],     qfh[kk], bh_[0], bh_[1]);
                mma16816(s[2 * jp],     qfh[kk], bl_[0], bl_[1]);
                mma16816(s[2 * jp],     qfl[kk], bh_[0], bh_[1]);
                mma16816(s[2 * jp + 1], qfh[kk], bh_[2], bh_[3]);
                mma16816(s[2 * jp + 1], qfh[kk], bl_[2], bl_[3]);
                mma16816(s[2 * jp + 1], qfl[kk], bh_[2], bh_[3]);
            }
        }

        const int rowa = qbase + r0 + g;
        const int rowb = rowa + 8;
        if (kt >= 2 * qblk) {
            const int kb = kt * 64;
#pragma unroll
            for (int jn = 0; jn < 8; jn++) {
                const int c0 = kb + jn * 8 + tg * 2;
                if (c0     > rowa) s[jn][0] = -INFINITY;
                if (c0 + 1 > rowa) s[jn][1] = -INFINITY;
                if (c0     > rowb) s[jn][2] = -INFINITY;
                if (c0 + 1 > rowb) s[jn][3] = -INFINITY;
            }
        }

        float mxa = -INFINITY, mxb = -INFINITY;
#pragma unroll
        for (int jn = 0; jn < 8; jn++) {
            mxa = fmaxf(mxa, fmaxf(s[jn][0], s[jn][1]));
            mxb = fmaxf(mxb, fmaxf(s[jn][2], s[jn][3]));
        }
        mxa = fmaxf(mxa, __shfl_xor_sync(0xffffffffu, mxa, 1));
        mxa = fmaxf(mxa, __shfl_xor_sync(0xffffffffu, mxa, 2));
        mxb = fmaxf(mxb, __shfl_xor_sync(0xffffffffu, mxb, 1));
        mxb = fmaxf(mxb, __shfl_xor_sync(0xffffffffu, mxb, 2));
        const float mna = fmaxf(m_a, mxa);
        const float mnb = fmaxf(m_b, mxb);
        float suma = 0.f, sumb = 0.f;
#pragma unroll
        for (int jn = 0; jn < 8; jn++) {
            s[jn][0] = __expf(s[jn][0] - mna);
            s[jn][1] = __expf(s[jn][1] - mna);
            s[jn][2] = __expf(s[jn][2] - mnb);
            s[jn][3] = __expf(s[jn][3] - mnb);
            suma += s[jn][0] + s[jn][1];
            sumb += s[jn][2] + s[jn][3];
        }
        suma += __shfl_xor_sync(0xffffffffu, suma, 1);
        suma += __shfl_xor_sync(0xffffffffu, suma, 2);
        sumb += __shfl_xor_sync(0xffffffffu, sumb, 1);
        sumb += __shfl_xor_sync(0xffffffffu, sumb, 2);
        const float aa = __expf(m_a - mna);
        const float ab = __expf(m_b - mnb);
        m_a = mna; m_b = mnb;
        l_a = l_a * aa + suma;
        l_b = l_b * ab + sumb;
#pragma unroll
        for (int jn = 0; jn < 8; jn++) {
            o[jn][0] *= aa; o[jn][1] *= aa;
            o[jn][2] *= ab; o[jn][3] *= ab;
        }

        uint32_t pah[4][4], pal[4][4];
#pragma unroll
        for (int jk = 0; jk < 4; jk++) {
            const int t0 = 2 * jk, t1 = t0 + 1;
            const float* p0 = s[t0];
            const float* p1 = s[t1];
            pah[jk][0] = f22h2(p0[0], p0[1]);
            pah[jk][1] = f22h2(p0[2], p0[3]);
            pah[jk][2] = f22h2(p1[0], p1[1]);
            pah[jk][3] = f22h2(p1[2], p1[3]);
            float2 r;
            r = h22f2(pah[jk][0]); pal[jk][0] = f22h2(p0[0] - r.x, p0[1] - r.y);
            r = h22f2(pah[jk][1]); pal[jk][1] = f22h2(p0[2] - r.x, p0[3] - r.y);
            r = h22f2(pah[jk][2]); pal[jk][2] = f22h2(p1[0] - r.x, p1[1] - r.y);
            r = h22f2(pah[jk][3]); pal[jk][3] = f22h2(p1[2] - r.x, p1[3] - r.y);
        }

#pragma unroll
        for (int jk = 0; jk < 4; jk++) {
#pragma unroll
            for (int jp = 0; jp < 4; jp++) {
                const uint32_t voff = ((uint32_t)(jk * 16) * KLD + jp * 16) * 2;
                uint32_t bh_[4], bl_[4];
                ldsm_x4_t(bh_, vu_h + vbasea + voff);
                ldsm_x4_t(bl_, vu_l + vbasea + voff);
                mma16816(o[2 * jp],     pah[jk], bh_[0], bh_[1]);
                mma16816(o[2 * jp],     pah[jk], bl_[0], bl_[1]);
                mma16816(o[2 * jp],     pal[jk], bh_[0], bh_[1]);
                mma16816(o[2 * jp + 1], pah[jk], bh_[2], bh_[3]);
                mma16816(o[2 * jp + 1], pah[jk], bl_[2], bl_[3]);
                mma16816(o[2 * jp + 1], pal[jk], bh_[2], bh_[3]);
            }
        }
    }

    {
        const float inva = 1.f / l_a;
        const float invb = 1.f / l_b;
        const int rowa = qbase + r0 + g;
        const size_t basea = (size_t)(b * LL + rowa) * DDM + h * DKK;
        const size_t baseb = basea + (size_t)8 * DDM;
#pragma unroll
        for (int jn = 0; jn < 8; jn++) {
            const int c = jn * 8 + tg * 2;
            float v0 = o[jn][0] * inva, v1 = o[jn][1] * inva;
            uint32_t hh = f22h2(v0, v1);
            float2 hf = h22f2(hh);
            uint32_t ll = f22h2(v0 - hf.x, v1 - hf.y);
            *(uint32_t*)&g_ah[basea + c] = hh;
            *(uint32_t*)&g_al[basea + c] = ll;
            v0 = o[jn][2] * invb; v1 = o[jn][3] * invb;
            hh = f22h2(v0, v1);
            hf = h22f2(hh);
            ll = f22h2(v0 - hf.x, v1 - hf.y);
            *(uint32_t*)&g_ah[baseb + c] = hh;
            *(uint32_t*)&g_al[baseb + c] = ll;
        }
    }
}

// ---------------------------------------------------------------------------
// Inputs (metadata order): Q, K, V, mask, Wq, bq, Wk, bk, Wv, bv, Wo, bo.
// ---------------------------------------------------------------------------
extern "C" void kernel_launch(void* const* d_in, const int* in_sizes, int n_in,
                              void* d_out, int out_size)
{
    const float* Q  = (const float*)d_in[0];
    const float* K  = (const float*)d_in[1];
    const float* V  = (const float*)d_in[2];
    const float* Wq = (const float*)d_in[4];
    const float* bq = (const float*)d_in[5];
    const float* Wk = (const float*)d_in[6];
    const float* bk = (const float*)d_in[7];
    const float* Wv = (const float*)d_in[8];
    const float* bv = (const float*)d_in[9];
    const float* Wo = (const float*)d_in[10];
    const float* bo = (const float*)d_in[11];
    float* out = (float*)d_out;

    cudaFuncSetAttribute(qkv_wmma_kernel,
                         cudaFuncAttributeMaxDynamicSharedMemorySize, SMEM_GEMM_BYTES);
    cudaFuncSetAttribute(out_wmma_kernel,
                         cudaFuncAttributeMaxDynamicSharedMemorySize, SMEM_GEMM_BYTES);
    cudaFuncSetAttribute(attn_mma_kernel,
                         cudaFuncAttributeMaxDynamicSharedMemorySize, ATTN_SMEM_BYTES);

    const int nI4 = MMR * DDM / 4;

    dim3 gcvt(nI4 / 256, 7);
    cvt_kernel<<<gcvt, 256>>>(Q, K, V, Wq, Wk, Wv, Wo);

    dim3 gqkv(DDM / 128, MMR / 256, 3);
    qkv_wmma_kernel<<<gqkv, 256, SMEM_GEMM_BYTES>>>(bq, bk, bv);

    dim3 gattn(LL / 128, BB * HH);
    attn_mma_kernel<<<gattn, 256, ATTN_SMEM_BYTES>>>();

    dim3 gout(DDM / 128, MMR / 256);
    out_wmma_kernel<<<gout, 256, SMEM_GEMM_BYTES>>>(bo, out);
}